// round 2
// baseline (speedup 1.0000x reference)
#include <cuda_runtime.h>

// Problem constants
#define BB 4
#define SS 2048
#define DD 1024
#define HH 16
#define DHH 64
#define MM (BB * SS)   // 8192 rows

// ---------------------------------------------------------------------------
// Scratch (device globals: allocation-free rule)
// ---------------------------------------------------------------------------
__device__ float g_q[MM * DD];
__device__ float g_k[MM * DD];
__device__ float g_v[MM * DD];
__device__ float g_attn[MM * DD];
__device__ float g_y[MM * DD];

// ---------------------------------------------------------------------------
// SGEMM: C[M,N] = A[M,K] @ W[K,N] + bias (+ residual). M=8192, N=K=1024.
// 128x128 block tile, BK=8, 256 threads, 8x8 per-thread microtile.
// A==nullptr means "read from g_attn". outsel picks the destination global.
// ---------------------------------------------------------------------------
__global__ __launch_bounds__(256) void sgemm_bias_kernel(
    const float* __restrict__ Ain, const float* __restrict__ W,
    const float* __restrict__ bias, const float* __restrict__ Res, int outsel)
{
    const float* A = Ain ? Ain : g_attn;
    float* C = (outsel == 0) ? g_q : (outsel == 1) ? g_k : (outsel == 2) ? g_v : g_y;

    __shared__ float As[8][128];
    __shared__ float Bs[8][128];

    const int tid  = threadIdx.x;
    const int brow = blockIdx.y * 128;
    const int bcol = blockIdx.x * 128;

    const int arow = tid >> 1;           // 0..127
    const int acol = (tid & 1) << 2;     // 0 or 4
    const int wrow = tid >> 5;           // 0..7
    const int wcol = (tid & 31) << 2;    // 0..124

    const int ty = tid >> 4;             // 0..15 -> rows ty*8..+7
    const int tx = tid & 15;             // 0..15 -> cols tx*8..+7

    float acc[8][8];
#pragma unroll
    for (int i = 0; i < 8; i++)
#pragma unroll
        for (int j = 0; j < 8; j++) acc[i][j] = 0.f;

    for (int k0 = 0; k0 < DD; k0 += 8) {
        float4 av = *reinterpret_cast<const float4*>(
            &A[(size_t)(brow + arow) * DD + k0 + acol]);
        float4 wv = *reinterpret_cast<const float4*>(
            &W[(size_t)(k0 + wrow) * DD + bcol + wcol]);

        As[acol + 0][arow] = av.x;
        As[acol + 1][arow] = av.y;
        As[acol + 2][arow] = av.z;
        As[acol + 3][arow] = av.w;
        *reinterpret_cast<float4*>(&Bs[wrow][wcol]) = wv;
        __syncthreads();

#pragma unroll
        for (int kk = 0; kk < 8; kk++) {
            float a[8], b[8];
            *reinterpret_cast<float4*>(&a[0]) = *reinterpret_cast<const float4*>(&As[kk][ty * 8]);
            *reinterpret_cast<float4*>(&a[4]) = *reinterpret_cast<const float4*>(&As[kk][ty * 8 + 4]);
            *reinterpret_cast<float4*>(&b[0]) = *reinterpret_cast<const float4*>(&Bs[kk][tx * 8]);
            *reinterpret_cast<float4*>(&b[4]) = *reinterpret_cast<const float4*>(&Bs[kk][tx * 8 + 4]);
#pragma unroll
            for (int i = 0; i < 8; i++)
#pragma unroll
                for (int j = 0; j < 8; j++) acc[i][j] += a[i] * b[j];
        }
        __syncthreads();
    }

#pragma unroll
    for (int i = 0; i < 8; i++) {
        const int row = brow + ty * 8 + i;
#pragma unroll
        for (int j0 = 0; j0 < 8; j0 += 4) {
            const int col = bcol + tx * 8 + j0;
            float4 bv = *reinterpret_cast<const float4*>(&bias[col]);
            float4 r;
            r.x = acc[i][j0 + 0] + bv.x;
            r.y = acc[i][j0 + 1] + bv.y;
            r.z = acc[i][j0 + 2] + bv.z;
            r.w = acc[i][j0 + 3] + bv.w;
            if (Res) {
                float4 rv = *reinterpret_cast<const float4*>(&Res[(size_t)row * DD + col]);
                r.x += rv.x; r.y += rv.y; r.z += rv.z; r.w += rv.w;
            }
            *reinterpret_cast<float4*>(&C[(size_t)row * DD + col]) = r;
        }
    }
}

// ---------------------------------------------------------------------------
// Flash attention for one (b,h): contiguous [2048,64] Q/K/V slabs.
// Block: 64 q-rows; loop 32 kv-tiles of 64. 256 threads = 16x16; each thread
// owns a 4x4 tile of S/P (rows 4ty+i, kv-cols 4tx+j) and a 4(row)x4(col) O.
// Qs/Ks stored d-major ([d][row]) for broadcast-friendly outer products.
// P reuses K's smem buffer (row-major [r][k]). Total smem = 48KB.
// ---------------------------------------------------------------------------
__global__ __launch_bounds__(256) void flash_attn_kernel()
{
    __shared__ float Qs[64][64];   // [d][r]
    __shared__ float KP[64 * 64];  // first Ks as [d][c]; then Ps as [r][k]
    __shared__ float Vs[64][64];   // [k][c]

    const int bh = blockIdx.y;              // 0..63 = b*H + h
    const int q0 = blockIdx.x * 64;
    const size_t base = (size_t)bh * SS * DHH;
    const float* Qh = g_q + base;
    const float* Kh = g_k + base;
    const float* Vh = g_v + base;
    float* Oh = g_attn + base;

    const int tid = threadIdx.x;
    const int ty = tid >> 4, tx = tid & 15;
    const int lr = tid >> 2;            // 0..63 (load row)
    const int lc = (tid & 3) << 4;      // 0,16,32,48 (load col start)

    // Load Q tile transposed into Qs[d][r]
#pragma unroll
    for (int u = 0; u < 4; u++) {
        float4 v = *reinterpret_cast<const float4*>(&Qh[(size_t)(q0 + lr) * DHH + lc + u * 4]);
        Qs[lc + u * 4 + 0][lr] = v.x;
        Qs[lc + u * 4 + 1][lr] = v.y;
        Qs[lc + u * 4 + 2][lr] = v.z;
        Qs[lc + u * 4 + 3][lr] = v.w;
    }

    float m[4], l[4], o[4][4];
#pragma unroll
    for (int i = 0; i < 4; i++) {
        m[i] = -1e30f; l[i] = 0.f;
#pragma unroll
        for (int j = 0; j < 4; j++) o[i][j] = 0.f;
    }

    for (int kt = 0; kt < SS / 64; kt++) {
        __syncthreads();  // previous iter done with KP (as P) and Vs
        // Load K transposed ([d][c]) and V straight ([k][c])
#pragma unroll
        for (int u = 0; u < 4; u++) {
            float4 kv = *reinterpret_cast<const float4*>(&Kh[(size_t)(kt * 64 + lr) * DHH + lc + u * 4]);
            KP[(lc + u * 4 + 0) * 64 + lr] = kv.x;
            KP[(lc + u * 4 + 1) * 64 + lr] = kv.y;
            KP[(lc + u * 4 + 2) * 64 + lr] = kv.z;
            KP[(lc + u * 4 + 3) * 64 + lr] = kv.w;
            float4 vv = *reinterpret_cast<const float4*>(&Vh[(size_t)(kt * 64 + lr) * DHH + lc + u * 4]);
            *reinterpret_cast<float4*>(&Vs[lr][lc + u * 4]) = vv;
        }
        __syncthreads();

        // S = Q @ K^T  (outer-product over d)
        float s[4][4];
#pragma unroll
        for (int i = 0; i < 4; i++)
#pragma unroll
            for (int j = 0; j < 4; j++) s[i][j] = 0.f;

#pragma unroll 16
        for (int d = 0; d < 64; d++) {
            float qf[4], kf[4];
            *reinterpret_cast<float4*>(qf) = *reinterpret_cast<const float4*>(&Qs[d][ty * 4]);
            *reinterpret_cast<float4*>(kf) = *reinterpret_cast<const float4*>(&KP[d * 64 + tx * 4]);
#pragma unroll
            for (int i = 0; i < 4; i++)
#pragma unroll
                for (int j = 0; j < 4; j++) s[i][j] += qf[i] * kf[j];
        }

        // Online softmax update (row stats shared by 16 lanes of same ty)
        float sc[4];
#pragma unroll
        for (int i = 0; i < 4; i++) {
            float v = fmaxf(fmaxf(s[i][0] * 0.125f, s[i][1] * 0.125f),
                            fmaxf(s[i][2] * 0.125f, s[i][3] * 0.125f));
#pragma unroll
            for (int off = 1; off < 16; off <<= 1)
                v = fmaxf(v, __shfl_xor_sync(0xffffffffu, v, off));
            float mnew = fmaxf(m[i], v);
            sc[i] = __expf(m[i] - mnew);
            m[i] = mnew;
        }
#pragma unroll
        for (int i = 0; i < 4; i++) {
            float rs = 0.f;
#pragma unroll
            for (int j = 0; j < 4; j++) {
                float p = __expf(s[i][j] * 0.125f - m[i]);
                s[i][j] = p;
                rs += p;
            }
#pragma unroll
            for (int off = 1; off < 16; off <<= 1)
                rs += __shfl_xor_sync(0xffffffffu, rs, off);
            l[i] = l[i] * sc[i] + rs;
#pragma unroll
            for (int j = 0; j < 4; j++) o[i][j] *= sc[i];
        }

        __syncthreads();  // everyone done reading KP as Ks
        // Store P row-major: Ps[r][k] with r=4ty+i, k=4tx+j (float4 per row)
#pragma unroll
        for (int i = 0; i < 4; i++) {
            float4 pv;
            pv.x = s[i][0]; pv.y = s[i][1]; pv.z = s[i][2]; pv.w = s[i][3];
            *reinterpret_cast<float4*>(&KP[(ty * 4 + i) * 64 + tx * 4]) = pv;
        }
        __syncthreads();

        // O += P @ V
#pragma unroll 16
        for (int k = 0; k < 64; k++) {
            float pf[4], vf[4];
            pf[0] = KP[(ty * 4 + 0) * 64 + k];
            pf[1] = KP[(ty * 4 + 1) * 64 + k];
            pf[2] = KP[(ty * 4 + 2) * 64 + k];
            pf[3] = KP[(ty * 4 + 3) * 64 + k];
            *reinterpret_cast<float4*>(vf) = *reinterpret_cast<const float4*>(&Vs[k][tx * 4]);
#pragma unroll
            for (int i = 0; i < 4; i++)
#pragma unroll
                for (int j = 0; j < 4; j++) o[i][j] += pf[i] * vf[j];
        }
    }

    // Normalize and write out
#pragma unroll
    for (int i = 0; i < 4; i++) {
        float inv = 1.0f / l[i];
        float4 r;
        r.x = o[i][0] * inv; r.y = o[i][1] * inv;
        r.z = o[i][2] * inv; r.w = o[i][3] * inv;
        *reinterpret_cast<float4*>(&Oh[(size_t)(q0 + ty * 4 + i) * DHH + tx * 4]) = r;
    }
}

// ---------------------------------------------------------------------------
// LayerNorm over rows of g_y -> d_out
// ---------------------------------------------------------------------------
__global__ __launch_bounds__(256) void ln_kernel(
    const float* __restrict__ gamma, const float* __restrict__ beta,
    float* __restrict__ out)
{
    const int row = blockIdx.x;
    const int tid = threadIdx.x;
    const float* y = g_y + (size_t)row * DD;

    float4 v = *reinterpret_cast<const float4*>(&y[tid * 4]);
    float sum = v.x + v.y + v.z + v.w;
    float sq  = v.x * v.x + v.y * v.y + v.z * v.z + v.w * v.w;

#pragma unroll
    for (int off = 16; off > 0; off >>= 1) {
        sum += __shfl_xor_sync(0xffffffffu, sum, off);
        sq  += __shfl_xor_sync(0xffffffffu, sq, off);
    }

    __shared__ float red[16];
    __shared__ float mean_s, rstd_s;
    const int warp = tid >> 5;
    if ((tid & 31) == 0) { red[warp] = sum; red[8 + warp] = sq; }
    __syncthreads();
    if (tid == 0) {
        float ts = 0.f, tq = 0.f;
#pragma unroll
        for (int w = 0; w < 8; w++) { ts += red[w]; tq += red[8 + w]; }
        float mu = ts * (1.0f / DD);
        float var = tq * (1.0f / DD) - mu * mu;
        mean_s = mu;
        rstd_s = rsqrtf(var + 1e-5f);
    }
    __syncthreads();
    const float mu = mean_s, rs = rstd_s;

    float4 g  = *reinterpret_cast<const float4*>(&gamma[tid * 4]);
    float4 bt = *reinterpret_cast<const float4*>(&beta[tid * 4]);
    float4 r;
    r.x = (v.x - mu) * rs * g.x + bt.x;
    r.y = (v.y - mu) * rs * g.y + bt.y;
    r.z = (v.z - mu) * rs * g.z + bt.z;
    r.w = (v.w - mu) * rs * g.w + bt.w;
    *reinterpret_cast<float4*>(&out[(size_t)row * DD + tid * 4]) = r;
}

// ---------------------------------------------------------------------------
extern "C" void kernel_launch(void* const* d_in, const int* in_sizes, int n_in,
                              void* d_out, int out_size)
{
    (void)in_sizes; (void)n_in; (void)out_size;
    const float* queries = (const float*)d_in[0];
    const float* keys    = (const float*)d_in[1];
    const float* values  = (const float*)d_in[2];
    const float* Wq = (const float*)d_in[3];
    const float* bq = (const float*)d_in[4];
    const float* Wk = (const float*)d_in[5];
    const float* bk = (const float*)d_in[6];
    const float* Wv = (const float*)d_in[7];
    const float* bv = (const float*)d_in[8];
    const float* Wo = (const float*)d_in[9];
    const float* bo = (const float*)d_in[10];
    const float* gamma = (const float*)d_in[11];
    const float* beta  = (const float*)d_in[12];

    dim3 gg(DD / 128, MM / 128);  // (8, 64)
    sgemm_bias_kernel<<<gg, 256>>>(queries, Wq, bq, nullptr, 0);
    sgemm_bias_kernel<<<gg, 256>>>(keys,    Wk, bk, nullptr, 1);
    sgemm_bias_kernel<<<gg, 256>>>(values,  Wv, bv, nullptr, 2);

    flash_attn_kernel<<<dim3(SS / 64, BB * HH), 256>>>();

    sgemm_bias_kernel<<<gg, 256>>>(nullptr, Wo, bo, queries, 3);

    ln_kernel<<<MM, 256>>>(gamma, beta, (float*)d_out);
}

// round 3
// speedup vs baseline: 2.8632x; 2.8632x over previous
#include <cuda_runtime.h>

#define BB 4
#define SS 2048
#define DD 1024
#define HH 16
#define DHH 64
#define MM (BB * SS)   // 8192

// ---------------------------------------------------------------------------
// Scratch (device globals: allocation-free rule)
// ---------------------------------------------------------------------------
__device__ float g_q[MM * DD];
__device__ float g_k[MM * DD];
__device__ float g_v[MM * DD];
__device__ float g_attn[MM * DD];
__device__ float g_y[MM * DD];

// ---------------------------------------------------------------------------
// tf32 helpers
// ---------------------------------------------------------------------------
__device__ __forceinline__ unsigned f2tf(float x) {
    unsigned r;
    asm("cvt.rna.tf32.f32 %0, %1;" : "=r"(r) : "f"(x));
    return r;
}

__device__ __forceinline__ void mma8(float& c0, float& c1, float& c2, float& c3,
                                     unsigned a0, unsigned a1, unsigned a2, unsigned a3,
                                     unsigned b0, unsigned b1) {
    asm volatile(
        "mma.sync.aligned.m16n8k8.row.col.f32.tf32.tf32.f32 "
        "{%0,%1,%2,%3},{%4,%5,%6,%7},{%8,%9},{%0,%1,%2,%3};"
        : "+f"(c0), "+f"(c1), "+f"(c2), "+f"(c3)
        : "r"(a0), "r"(a1), "r"(a2), "r"(a3), "r"(b0), "r"(b1));
}

// ---------------------------------------------------------------------------
// TF32 GEMM: C[M,N] = A[M,K] @ W[K,N] + bias (+ residual)
// M=8192, N=K=1024. Block 128x128, BK=16, 256 thr, warp tile 64x32.
// ---------------------------------------------------------------------------
#define AST 20    // As row stride (words): conflict-free frag reads
#define BST 136   // Bs row stride (words): conflict-free frag reads

__global__ __launch_bounds__(256) void gemm_tf32_kernel(
    const float* __restrict__ Ain, const float* __restrict__ W,
    const float* __restrict__ bias, const float* __restrict__ Res, int outsel)
{
    const float* A = Ain ? Ain : g_attn;
    float* C = (outsel == 0) ? g_q : (outsel == 1) ? g_k : (outsel == 2) ? g_v : g_y;

    __shared__ unsigned As[128 * AST];
    __shared__ unsigned Bs[16 * BST];

    const int tid  = threadIdx.x;
    const int lane = tid & 31;
    const int warp = tid >> 5;
    const int wm   = warp >> 2;   // 0..1 -> 64 rows
    const int wn   = warp & 3;    // 0..3 -> 32 cols
    const int gid  = lane >> 2;   // 0..7
    const int tig  = lane & 3;    // 0..3
    const int brow = blockIdx.y * 128;
    const int bcol = blockIdx.x * 128;

    float acc[4][4][4];
#pragma unroll
    for (int mt = 0; mt < 4; mt++)
#pragma unroll
        for (int nt = 0; nt < 4; nt++)
#pragma unroll
            for (int r = 0; r < 4; r++) acc[mt][nt][r] = 0.f;

    const int ar  = tid >> 2;          // 0..63 (A rows, +64 second)
    const int ac  = (tid & 3) * 4;     // 0,4,8,12
    const int brB = tid >> 5;          // 0..7 (B k-rows, +8 second)
    const int bcB = (tid & 31) * 4;    // 0..124

    // register prefetch of tile 0
    float4 a0v = *(const float4*)&A[(size_t)(brow + ar) * DD + ac];
    float4 a1v = *(const float4*)&A[(size_t)(brow + ar + 64) * DD + ac];
    float4 b0v = *(const float4*)&W[(size_t)brB * DD + bcol + bcB];
    float4 b1v = *(const float4*)&W[(size_t)(brB + 8) * DD + bcol + bcB];

    for (int it = 0; it < DD / 16; it++) {
        As[ar * AST + ac + 0] = f2tf(a0v.x);
        As[ar * AST + ac + 1] = f2tf(a0v.y);
        As[ar * AST + ac + 2] = f2tf(a0v.z);
        As[ar * AST + ac + 3] = f2tf(a0v.w);
        As[(ar + 64) * AST + ac + 0] = f2tf(a1v.x);
        As[(ar + 64) * AST + ac + 1] = f2tf(a1v.y);
        As[(ar + 64) * AST + ac + 2] = f2tf(a1v.z);
        As[(ar + 64) * AST + ac + 3] = f2tf(a1v.w);
        Bs[brB * BST + bcB + 0] = f2tf(b0v.x);
        Bs[brB * BST + bcB + 1] = f2tf(b0v.y);
        Bs[brB * BST + bcB + 2] = f2tf(b0v.z);
        Bs[brB * BST + bcB + 3] = f2tf(b0v.w);
        Bs[(brB + 8) * BST + bcB + 0] = f2tf(b1v.x);
        Bs[(brB + 8) * BST + bcB + 1] = f2tf(b1v.y);
        Bs[(brB + 8) * BST + bcB + 2] = f2tf(b1v.z);
        Bs[(brB + 8) * BST + bcB + 3] = f2tf(b1v.w);
        __syncthreads();

        if (it < DD / 16 - 1) {
            const int k0 = (it + 1) * 16;
            a0v = *(const float4*)&A[(size_t)(brow + ar) * DD + k0 + ac];
            a1v = *(const float4*)&A[(size_t)(brow + ar + 64) * DD + k0 + ac];
            b0v = *(const float4*)&W[(size_t)(k0 + brB) * DD + bcol + bcB];
            b1v = *(const float4*)&W[(size_t)(k0 + brB + 8) * DD + bcol + bcB];
        }

#pragma unroll
        for (int ks = 0; ks < 2; ks++) {
            unsigned af[4][4];
#pragma unroll
            for (int mt = 0; mt < 4; mt++) {
                const int r = wm * 64 + mt * 16 + gid;
                const int c = ks * 8 + tig;
                af[mt][0] = As[r * AST + c];
                af[mt][1] = As[(r + 8) * AST + c];
                af[mt][2] = As[r * AST + c + 4];
                af[mt][3] = As[(r + 8) * AST + c + 4];
            }
            unsigned bf[4][2];
#pragma unroll
            for (int nt = 0; nt < 4; nt++) {
                const int kr = ks * 8 + tig;
                const int nc = wn * 32 + nt * 8 + gid;
                bf[nt][0] = Bs[kr * BST + nc];
                bf[nt][1] = Bs[(kr + 4) * BST + nc];
            }
#pragma unroll
            for (int mt = 0; mt < 4; mt++)
#pragma unroll
                for (int nt = 0; nt < 4; nt++)
                    mma8(acc[mt][nt][0], acc[mt][nt][1], acc[mt][nt][2], acc[mt][nt][3],
                         af[mt][0], af[mt][1], af[mt][2], af[mt][3],
                         bf[nt][0], bf[nt][1]);
        }
        __syncthreads();
    }

    // epilogue
#pragma unroll
    for (int mt = 0; mt < 4; mt++) {
        const int r0 = brow + wm * 64 + mt * 16 + gid;
#pragma unroll
        for (int nt = 0; nt < 4; nt++) {
            const int c = bcol + wn * 32 + nt * 8 + tig * 2;
            const float bz0 = bias[c], bz1 = bias[c + 1];
            float x0 = acc[mt][nt][0] + bz0;
            float x1 = acc[mt][nt][1] + bz1;
            float x2 = acc[mt][nt][2] + bz0;
            float x3 = acc[mt][nt][3] + bz1;
            if (Res) {
                x0 += Res[(size_t)r0 * DD + c];
                x1 += Res[(size_t)r0 * DD + c + 1];
                x2 += Res[(size_t)(r0 + 8) * DD + c];
                x3 += Res[(size_t)(r0 + 8) * DD + c + 1];
            }
            float2 lo = {x0, x1}, hi = {x2, x3};
            *(float2*)&C[(size_t)r0 * DD + c] = lo;
            *(float2*)&C[(size_t)(r0 + 8) * DD + c] = hi;
        }
    }
}

// ---------------------------------------------------------------------------
// TF32 flash attention: one (b,h) slab [2048,64]; block = 128 q rows, 8 warps,
// warp owns 16 q rows. Q frags in registers. KV tiles of 64.
// smem strides chosen for conflict-free mma fragment LDS.
// ---------------------------------------------------------------------------
#define KST 68
#define VST 72
#define PST 68
#define OFF_K 0
#define OFF_V (64 * KST)                    // 4352
#define OFF_P (OFF_V + 64 * VST)            // 8960
#define ATTN_SMEM_WORDS (OFF_P + 128 * PST) // 17664
#define ATTN_SMEM_BYTES (ATTN_SMEM_WORDS * 4)

__global__ __launch_bounds__(256) void attn_tf32_kernel()
{
    extern __shared__ unsigned sm[];
    unsigned* Ks = sm + OFF_K;
    unsigned* Vs = sm + OFF_V;
    unsigned* Ps = sm + OFF_P;

    const int tid  = threadIdx.x;
    const int lane = tid & 31;
    const int warp = tid >> 5;
    const int gid  = lane >> 2;
    const int tig  = lane & 3;

    const int bh = blockIdx.y;
    const int q0 = blockIdx.x * 128;
    const size_t base = (size_t)bh * SS * DHH;
    const float* Qh = g_q + base;
    const float* Kh = g_k + base;
    const float* Vh = g_v + base;
    float* Oh = g_attn + base;

    // Q fragments (row-major A, 8 k-steps over d=64)
    unsigned qa[8][4];
    const int qr = q0 + warp * 16 + gid;
#pragma unroll
    for (int ks = 0; ks < 8; ks++) {
        const int c = ks * 8 + tig;
        qa[ks][0] = f2tf(Qh[(size_t)qr * DHH + c]);
        qa[ks][1] = f2tf(Qh[(size_t)(qr + 8) * DHH + c]);
        qa[ks][2] = f2tf(Qh[(size_t)qr * DHH + c + 4]);
        qa[ks][3] = f2tf(Qh[(size_t)(qr + 8) * DHH + c + 4]);
    }

    float m0 = -1e30f, m1 = -1e30f, l0 = 0.f, l1 = 0.f;
    float o[8][4];
#pragma unroll
    for (int nt = 0; nt < 8; nt++)
#pragma unroll
        for (int r = 0; r < 4; r++) o[nt][r] = 0.f;

    const int lr = tid >> 4;        // 0..15
    const int lc = (tid & 15) * 4;  // 0..60
    const float scale = 0.125f;

    for (int kt = 0; kt < SS / 64; kt++) {
        __syncthreads();
        const float* Kp = Kh + (size_t)(kt * 64) * DHH;
        const float* Vp = Vh + (size_t)(kt * 64) * DHH;
#pragma unroll
        for (int u = 0; u < 4; u++) {
            const int r = u * 16 + lr;
            float4 kv = *(const float4*)&Kp[r * DHH + lc];
            Ks[r * KST + lc + 0] = f2tf(kv.x);
            Ks[r * KST + lc + 1] = f2tf(kv.y);
            Ks[r * KST + lc + 2] = f2tf(kv.z);
            Ks[r * KST + lc + 3] = f2tf(kv.w);
            float4 vv = *(const float4*)&Vp[r * DHH + lc];
            Vs[r * VST + lc + 0] = f2tf(vv.x);
            Vs[r * VST + lc + 1] = f2tf(vv.y);
            Vs[r * VST + lc + 2] = f2tf(vv.z);
            Vs[r * VST + lc + 3] = f2tf(vv.w);
        }
        __syncthreads();

        // S = Q @ K^T : sacc[nt] covers kv cols nt*8..+7
        float sacc[8][4];
#pragma unroll
        for (int nt = 0; nt < 8; nt++) {
            sacc[nt][0] = sacc[nt][1] = sacc[nt][2] = sacc[nt][3] = 0.f;
#pragma unroll
            for (int ks = 0; ks < 8; ks++) {
                const int d = ks * 8 + tig;
                const int j = nt * 8 + gid;
                const unsigned b0 = Ks[j * KST + d];
                const unsigned b1 = Ks[j * KST + d + 4];
                mma8(sacc[nt][0], sacc[nt][1], sacc[nt][2], sacc[nt][3],
                     qa[ks][0], qa[ks][1], qa[ks][2], qa[ks][3], b0, b1);
            }
        }

        // online softmax: rows qr (regs 0,1) and qr+8 (regs 2,3)
        float rm0 = -1e30f, rm1 = -1e30f;
#pragma unroll
        for (int nt = 0; nt < 8; nt++) {
            rm0 = fmaxf(rm0, fmaxf(sacc[nt][0], sacc[nt][1]));
            rm1 = fmaxf(rm1, fmaxf(sacc[nt][2], sacc[nt][3]));
        }
        rm0 *= scale; rm1 *= scale;
        rm0 = fmaxf(rm0, __shfl_xor_sync(0xffffffffu, rm0, 1));
        rm0 = fmaxf(rm0, __shfl_xor_sync(0xffffffffu, rm0, 2));
        rm1 = fmaxf(rm1, __shfl_xor_sync(0xffffffffu, rm1, 1));
        rm1 = fmaxf(rm1, __shfl_xor_sync(0xffffffffu, rm1, 2));
        const float nm0 = fmaxf(m0, rm0);
        const float nm1 = fmaxf(m1, rm1);
        const float al0 = __expf(m0 - nm0);
        const float al1 = __expf(m1 - nm1);
        m0 = nm0; m1 = nm1;

        float rs0 = 0.f, rs1 = 0.f;
#pragma unroll
        for (int nt = 0; nt < 8; nt++) {
            const float p0 = __expf(sacc[nt][0] * scale - m0);
            const float p1 = __expf(sacc[nt][1] * scale - m0);
            const float p2 = __expf(sacc[nt][2] * scale - m1);
            const float p3 = __expf(sacc[nt][3] * scale - m1);
            rs0 += p0 + p1; rs1 += p2 + p3;
            sacc[nt][0] = p0; sacc[nt][1] = p1; sacc[nt][2] = p2; sacc[nt][3] = p3;
        }
        rs0 += __shfl_xor_sync(0xffffffffu, rs0, 1);
        rs0 += __shfl_xor_sync(0xffffffffu, rs0, 2);
        rs1 += __shfl_xor_sync(0xffffffffu, rs1, 1);
        rs1 += __shfl_xor_sync(0xffffffffu, rs1, 2);
        l0 = l0 * al0 + rs0;
        l1 = l1 * al1 + rs1;
#pragma unroll
        for (int nt = 0; nt < 8; nt++) {
            o[nt][0] *= al0; o[nt][1] *= al0;
            o[nt][2] *= al1; o[nt][3] *= al1;
        }

        // P -> per-warp smem (re-fragment C-layout -> A-layout)
        const int prow = warp * 16 + gid;
#pragma unroll
        for (int nt = 0; nt < 8; nt++) {
            const int pc = nt * 8 + tig * 2;
            uint2 lo = {f2tf(sacc[nt][0]), f2tf(sacc[nt][1])};
            uint2 hi = {f2tf(sacc[nt][2]), f2tf(sacc[nt][3])};
            *(uint2*)&Ps[prow * PST + pc] = lo;
            *(uint2*)&Ps[(prow + 8) * PST + pc] = hi;
        }
        __syncwarp();

        // O += P @ V
#pragma unroll
        for (int ks = 0; ks < 8; ks++) {
            const unsigned p0 = Ps[(warp * 16 + gid) * PST + ks * 8 + tig];
            const unsigned p1 = Ps[(warp * 16 + gid + 8) * PST + ks * 8 + tig];
            const unsigned p2 = Ps[(warp * 16 + gid) * PST + ks * 8 + tig + 4];
            const unsigned p3 = Ps[(warp * 16 + gid + 8) * PST + ks * 8 + tig + 4];
#pragma unroll
            for (int nt = 0; nt < 8; nt++) {
                const unsigned b0 = Vs[(ks * 8 + tig) * VST + nt * 8 + gid];
                const unsigned b1 = Vs[(ks * 8 + tig + 4) * VST + nt * 8 + gid];
                mma8(o[nt][0], o[nt][1], o[nt][2], o[nt][3], p0, p1, p2, p3, b0, b1);
            }
        }
    }

    const float inv0 = 1.0f / l0;
    const float inv1 = 1.0f / l1;
#pragma unroll
    for (int nt = 0; nt < 8; nt++) {
        const int c = nt * 8 + tig * 2;
        float2 lo = {o[nt][0] * inv0, o[nt][1] * inv0};
        float2 hi = {o[nt][2] * inv1, o[nt][3] * inv1};
        *(float2*)&Oh[(size_t)qr * DHH + c] = lo;
        *(float2*)&Oh[(size_t)(qr + 8) * DHH + c] = hi;
    }
}

// ---------------------------------------------------------------------------
// LayerNorm over rows of g_y -> d_out
// ---------------------------------------------------------------------------
__global__ __launch_bounds__(256) void ln_kernel(
    const float* __restrict__ gamma, const float* __restrict__ beta,
    float* __restrict__ out)
{
    const int row = blockIdx.x;
    const int tid = threadIdx.x;
    const float* y = g_y + (size_t)row * DD;

    float4 v = *reinterpret_cast<const float4*>(&y[tid * 4]);
    float sum = v.x + v.y + v.z + v.w;
    float sq  = v.x * v.x + v.y * v.y + v.z * v.z + v.w * v.w;

#pragma unroll
    for (int off = 16; off > 0; off >>= 1) {
        sum += __shfl_xor_sync(0xffffffffu, sum, off);
        sq  += __shfl_xor_sync(0xffffffffu, sq, off);
    }

    __shared__ float red[16];
    __shared__ float mean_s, rstd_s;
    const int warp = tid >> 5;
    if ((tid & 31) == 0) { red[warp] = sum; red[8 + warp] = sq; }
    __syncthreads();
    if (tid == 0) {
        float ts = 0.f, tq = 0.f;
#pragma unroll
        for (int w = 0; w < 8; w++) { ts += red[w]; tq += red[8 + w]; }
        float mu = ts * (1.0f / DD);
        float var = tq * (1.0f / DD) - mu * mu;
        mean_s = mu;
        rstd_s = rsqrtf(var + 1e-5f);
    }
    __syncthreads();
    const float mu = mean_s, rs = rstd_s;

    float4 g  = *reinterpret_cast<const float4*>(&gamma[tid * 4]);
    float4 bt = *reinterpret_cast<const float4*>(&beta[tid * 4]);
    float4 r;
    r.x = (v.x - mu) * rs * g.x + bt.x;
    r.y = (v.y - mu) * rs * g.y + bt.y;
    r.z = (v.z - mu) * rs * g.z + bt.z;
    r.w = (v.w - mu) * rs * g.w + bt.w;
    *reinterpret_cast<float4*>(&out[(size_t)row * DD + tid * 4]) = r;
}

// ---------------------------------------------------------------------------
extern "C" void kernel_launch(void* const* d_in, const int* in_sizes, int n_in,
                              void* d_out, int out_size)
{
    (void)in_sizes; (void)n_in; (void)out_size;
    const float* queries = (const float*)d_in[0];
    const float* keys    = (const float*)d_in[1];
    const float* values  = (const float*)d_in[2];
    const float* Wq = (const float*)d_in[3];
    const float* bq = (const float*)d_in[4];
    const float* Wk = (const float*)d_in[5];
    const float* bk = (const float*)d_in[6];
    const float* Wv = (const float*)d_in[7];
    const float* bv = (const float*)d_in[8];
    const float* Wo = (const float*)d_in[9];
    const float* bo = (const float*)d_in[10];
    const float* gamma = (const float*)d_in[11];
    const float* beta  = (const float*)d_in[12];

    cudaFuncSetAttribute(attn_tf32_kernel,
                         cudaFuncAttributeMaxDynamicSharedMemorySize,
                         ATTN_SMEM_BYTES);

    dim3 gg(DD / 128, MM / 128);  // (8, 64)
    gemm_tf32_kernel<<<gg, 256>>>(queries, Wq, bq, nullptr, 0);
    gemm_tf32_kernel<<<gg, 256>>>(keys,    Wk, bk, nullptr, 1);
    gemm_tf32_kernel<<<gg, 256>>>(values,  Wv, bv, nullptr, 2);

    attn_tf32_kernel<<<dim3(SS / 128, BB * HH), 256, ATTN_SMEM_BYTES>>>();

    gemm_tf32_kernel<<<gg, 256>>>(nullptr, Wo, bo, queries, 3);

    ln_kernel<<<MM, 256>>>(gamma, beta, (float*)d_out);
}

// round 5
// speedup vs baseline: 4.4105x; 1.5404x over previous
#include <cuda_runtime.h>

#define BB 4
#define SS 2048
#define DD 1024
#define HH 16
#define DHH 64
#define MM (BB * SS)   // 8192

// ---------------------------------------------------------------------------
// Scratch (device globals: allocation-free rule)
// ---------------------------------------------------------------------------
__device__ float g_q[MM * DD];
__device__ float g_k[MM * DD];
__device__ float g_v[MM * DD];
__device__ float g_attn[MM * DD];
__device__ float g_y[MM * DD];

// ---------------------------------------------------------------------------
// helpers
// ---------------------------------------------------------------------------
__device__ __forceinline__ unsigned pk(float lo, float hi) {
    unsigned r;
    asm("cvt.rn.bf16x2.f32 %0, %1, %2;" : "=r"(r) : "f"(hi), "f"(lo));
    return r;
}

__device__ __forceinline__ void mma16(float& c0, float& c1, float& c2, float& c3,
                                      unsigned a0, unsigned a1, unsigned a2, unsigned a3,
                                      unsigned b0, unsigned b1) {
    asm volatile(
        "mma.sync.aligned.m16n8k16.row.col.f32.bf16.bf16.f32 "
        "{%0,%1,%2,%3},{%4,%5,%6,%7},{%8,%9},{%0,%1,%2,%3};"
        : "+f"(c0), "+f"(c1), "+f"(c2), "+f"(c3)
        : "r"(a0), "r"(a1), "r"(a2), "r"(a3), "r"(b0), "r"(b1));
}

__device__ __forceinline__ void ldmx4(unsigned& r0, unsigned& r1, unsigned& r2, unsigned& r3,
                                      unsigned addr) {
    asm volatile("ldmatrix.sync.aligned.m8n8.x4.shared.b16 {%0,%1,%2,%3}, [%4];"
                 : "=r"(r0), "=r"(r1), "=r"(r2), "=r"(r3) : "r"(addr));
}

__device__ __forceinline__ void ldmx4t(unsigned& r0, unsigned& r1, unsigned& r2, unsigned& r3,
                                       unsigned addr) {
    asm volatile("ldmatrix.sync.aligned.m8n8.x4.trans.shared.b16 {%0,%1,%2,%3}, [%4];"
                 : "=r"(r0), "=r"(r1), "=r"(r2), "=r"(r3) : "r"(addr));
}

// ---------------------------------------------------------------------------
// BF16 GEMM: C[M,N] = A[M,K] @ W[K,N] + bias (+ residual)
// Block 128x128, BK=32, 256 thr, warp tile 64x32, m16n8k16 mma + ldmatrix.
// As stride 40 bf16 (80B), Bs stride 136 bf16 (272B): ldmatrix conflict-free.
// ---------------------------------------------------------------------------
#define ASTW 20   // words per As row (40 bf16)
#define BSTW 68   // words per Bs row (136 bf16)

__global__ __launch_bounds__(256, 2) void gemm_bf16_kernel(
    const float* __restrict__ Ain, const float* __restrict__ W,
    const float* __restrict__ bias, const float* __restrict__ Res, int outsel)
{
    const float* A = Ain ? Ain : g_attn;
    float* C = (outsel == 0) ? g_q : (outsel == 1) ? g_k : (outsel == 2) ? g_v : g_y;

    __shared__ unsigned As[128 * ASTW];  // 10240 B
    __shared__ unsigned Bs[32 * BSTW];   //  8704 B

    const int tid  = threadIdx.x;
    const int lane = tid & 31;
    const int warp = tid >> 5;
    const int wm   = warp >> 2;
    const int wn   = warp & 3;
    const int gid  = lane >> 2;
    const int tig  = lane & 3;
    const int brow = blockIdx.y * 128;
    const int bcol = blockIdx.x * 128;

    float acc[4][4][4];
#pragma unroll
    for (int mt = 0; mt < 4; mt++)
#pragma unroll
        for (int nt = 0; nt < 4; nt++)
#pragma unroll
            for (int r = 0; r < 4; r++) acc[mt][nt][r] = 0.f;

    const int ar  = tid >> 1;          // 0..127
    const int acg = (tid & 1) * 16;    // 0 or 16
    const int kr  = tid >> 3;          // 0..31
    const int ncg = (tid & 7) * 16;    // 0..112

    float4 av[4], bv[4];
#pragma unroll
    for (int u = 0; u < 4; u++) {
        av[u] = *(const float4*)&A[(size_t)(brow + ar) * DD + acg + 4 * u];
        bv[u] = *(const float4*)&W[(size_t)kr * DD + bcol + ncg + 4 * u];
    }

    const unsigned aBase = (unsigned)__cvta_generic_to_shared(As);
    const unsigned bBase = (unsigned)__cvta_generic_to_shared(Bs);
    // lane-dependent ldmatrix address components
    const int arow_l = wm * 64 + (lane & 15);
    const int asel   = (lane >> 4) * 8;     // 0 or 8 (k halves)
    const int brow_l = lane & 15;           // k rows within step
    const int bsel   = (lane >> 4) * 8;     // 0 or 8 (n halves)

    for (int it = 0; it < DD / 32; it++) {
#pragma unroll
        for (int u = 0; u < 4; u++) {
            As[ar * ASTW + ((acg + 4 * u) >> 1) + 0] = pk(av[u].x, av[u].y);
            As[ar * ASTW + ((acg + 4 * u) >> 1) + 1] = pk(av[u].z, av[u].w);
            Bs[kr * BSTW + ((ncg + 4 * u) >> 1) + 0] = pk(bv[u].x, bv[u].y);
            Bs[kr * BSTW + ((ncg + 4 * u) >> 1) + 1] = pk(bv[u].z, bv[u].w);
        }
        __syncthreads();

        if (it < DD / 32 - 1) {
            const int k0 = (it + 1) * 32;
#pragma unroll
            for (int u = 0; u < 4; u++) {
                av[u] = *(const float4*)&A[(size_t)(brow + ar) * DD + k0 + acg + 4 * u];
                bv[u] = *(const float4*)&W[(size_t)(k0 + kr) * DD + bcol + ncg + 4 * u];
            }
        }

#pragma unroll
        for (int ks = 0; ks < 2; ks++) {
            unsigned af[4][4];
#pragma unroll
            for (int mt = 0; mt < 4; mt++)
                ldmx4(af[mt][0], af[mt][1], af[mt][2], af[mt][3],
                      aBase + (unsigned)(((arow_l + mt * 16) * ASTW + ((ks * 16 + asel) >> 1)) * 4));

            unsigned bf[4][2];
#pragma unroll
            for (int ntp = 0; ntp < 2; ntp++) {
                unsigned r0, r1, r2, r3;
                ldmx4t(r0, r1, r2, r3,
                       bBase + (unsigned)(((ks * 16 + brow_l) * BSTW +
                                           ((wn * 32 + ntp * 16 + bsel) >> 1)) * 4));
                bf[2 * ntp + 0][0] = r0; bf[2 * ntp + 0][1] = r1;
                bf[2 * ntp + 1][0] = r2; bf[2 * ntp + 1][1] = r3;
            }
#pragma unroll
            for (int mt = 0; mt < 4; mt++)
#pragma unroll
                for (int nt = 0; nt < 4; nt++)
                    mma16(acc[mt][nt][0], acc[mt][nt][1], acc[mt][nt][2], acc[mt][nt][3],
                          af[mt][0], af[mt][1], af[mt][2], af[mt][3],
                          bf[nt][0], bf[nt][1]);
        }
        __syncthreads();
    }

    // epilogue (C frag: c0,c1 = row gid cols 2tig,2tig+1; c2,c3 = row gid+8)
#pragma unroll
    for (int mt = 0; mt < 4; mt++) {
        const int r0 = brow + wm * 64 + mt * 16 + gid;
#pragma unroll
        for (int nt = 0; nt < 4; nt++) {
            const int c = bcol + wn * 32 + nt * 8 + tig * 2;
            const float bz0 = bias[c], bz1 = bias[c + 1];
            float x0 = acc[mt][nt][0] + bz0;
            float x1 = acc[mt][nt][1] + bz1;
            float x2 = acc[mt][nt][2] + bz0;
            float x3 = acc[mt][nt][3] + bz1;
            if (Res) {
                x0 += Res[(size_t)r0 * DD + c];
                x1 += Res[(size_t)r0 * DD + c + 1];
                x2 += Res[(size_t)(r0 + 8) * DD + c];
                x3 += Res[(size_t)(r0 + 8) * DD + c + 1];
            }
            float2 lo = {x0, x1}, hi = {x2, x3};
            *(float2*)&C[(size_t)r0 * DD + c] = lo;
            *(float2*)&C[(size_t)(r0 + 8) * DD + c] = hi;
        }
    }
}

// ---------------------------------------------------------------------------
// BF16 flash attention: one (b,h) slab [2048,64]; block = 128 q rows, 8 warps,
// warp owns 16 q rows. Q frags in registers (bf16). KV tiles of 64.
// K/V in smem bf16, stride 72 bf16 (144B) -> conflict-free ldmatrix.
// P never touches smem: C-frag -> A-frag via register bf16x2 packing.
// ---------------------------------------------------------------------------
#define KVST 36   // words per K/V row (72 bf16)

__global__ __launch_bounds__(256, 2) void attn_bf16_kernel()
{
    __shared__ unsigned Ks[64 * KVST];  // 9216 B
    __shared__ unsigned Vs[64 * KVST];  // 9216 B

    const int tid  = threadIdx.x;
    const int lane = tid & 31;
    const int warp = tid >> 5;
    const int gid  = lane >> 2;
    const int tig  = lane & 3;

    const int bh = blockIdx.y;
    const int q0 = blockIdx.x * 128;
    const size_t base = (size_t)bh * SS * DHH;
    const float* Qh = g_q + base;
    const float* Kh = g_k + base;
    const float* Vh = g_v + base;
    float* Oh = g_attn + base;

    // Q fragments (bf16 packed), 4 k-steps over d=64
    unsigned qa[4][4];
    const int qr = q0 + warp * 16 + gid;
#pragma unroll
    for (int ks = 0; ks < 4; ks++) {
        const int c = ks * 16 + 2 * tig;
        float2 x0 = *(const float2*)&Qh[(size_t)qr * DHH + c];
        float2 x1 = *(const float2*)&Qh[(size_t)(qr + 8) * DHH + c];
        float2 x2 = *(const float2*)&Qh[(size_t)qr * DHH + c + 8];
        float2 x3 = *(const float2*)&Qh[(size_t)(qr + 8) * DHH + c + 8];
        qa[ks][0] = pk(x0.x, x0.y);
        qa[ks][1] = pk(x1.x, x1.y);
        qa[ks][2] = pk(x2.x, x2.y);
        qa[ks][3] = pk(x3.x, x3.y);
    }

    float m0 = -1e30f, m1 = -1e30f, l0 = 0.f, l1 = 0.f;
    float o[8][4];
#pragma unroll
    for (int nt = 0; nt < 8; nt++)
#pragma unroll
        for (int r = 0; r < 4; r++) o[nt][r] = 0.f;

    const int lr  = tid >> 2;         // 0..63
    const int lcg = (tid & 3) * 16;   // 0..48
    const float scale = 0.125f;

    const unsigned kBase = (unsigned)__cvta_generic_to_shared(Ks);
    const unsigned vBase = (unsigned)__cvta_generic_to_shared(Vs);
    const int krow_l = lane & 7;      // S ldmatrix row within 8-row group
    const int kgsel  = (lane >> 3) * 4;  // word offset of 8-elem k group (0,4,8,12)

    for (int kt = 0; kt < SS / 64; kt++) {
        __syncthreads();
        const float* Kp = Kh + (size_t)(kt * 64) * DHH;
        const float* Vp = Vh + (size_t)(kt * 64) * DHH;
#pragma unroll
        for (int u = 0; u < 4; u++) {
            const int c = lcg + 4 * u;
            float4 kv = *(const float4*)&Kp[lr * DHH + c];
            Ks[lr * KVST + (c >> 1) + 0] = pk(kv.x, kv.y);
            Ks[lr * KVST + (c >> 1) + 1] = pk(kv.z, kv.w);
            float4 vv = *(const float4*)&Vp[lr * DHH + c];
            Vs[lr * KVST + (c >> 1) + 0] = pk(vv.x, vv.y);
            Vs[lr * KVST + (c >> 1) + 1] = pk(vv.z, vv.w);
        }
        __syncthreads();

        // S = Q @ K^T
        float sacc[8][4];
#pragma unroll
        for (int nt = 0; nt < 8; nt++) {
            sacc[nt][0] = sacc[nt][1] = sacc[nt][2] = sacc[nt][3] = 0.f;
            unsigned b0, b1, b2, b3, b4, b5, b6, b7;
            const unsigned rowoff = (unsigned)(((nt * 8 + krow_l) * KVST) * 4);
            ldmx4(b0, b1, b2, b3, kBase + rowoff + (unsigned)(kgsel * 4));        // k 0..31
            ldmx4(b4, b5, b6, b7, kBase + rowoff + (unsigned)((16 + kgsel) * 4)); // k 32..63
            mma16(sacc[nt][0], sacc[nt][1], sacc[nt][2], sacc[nt][3],
                  qa[0][0], qa[0][1], qa[0][2], qa[0][3], b0, b1);
            mma16(sacc[nt][0], sacc[nt][1], sacc[nt][2], sacc[nt][3],
                  qa[1][0], qa[1][1], qa[1][2], qa[1][3], b2, b3);
            mma16(sacc[nt][0], sacc[nt][1], sacc[nt][2], sacc[nt][3],
                  qa[2][0], qa[2][1], qa[2][2], qa[2][3], b4, b5);
            mma16(sacc[nt][0], sacc[nt][1], sacc[nt][2], sacc[nt][3],
                  qa[3][0], qa[3][1], qa[3][2], qa[3][3], b6, b7);
        }

        // online softmax (rows qr / qr+8; stats shared across tig lanes)
        float rm0 = -1e30f, rm1 = -1e30f;
#pragma unroll
        for (int nt = 0; nt < 8; nt++) {
            rm0 = fmaxf(rm0, fmaxf(sacc[nt][0], sacc[nt][1]));
            rm1 = fmaxf(rm1, fmaxf(sacc[nt][2], sacc[nt][3]));
        }
        rm0 *= scale; rm1 *= scale;
        rm0 = fmaxf(rm0, __shfl_xor_sync(0xffffffffu, rm0, 1));
        rm0 = fmaxf(rm0, __shfl_xor_sync(0xffffffffu, rm0, 2));
        rm1 = fmaxf(rm1, __shfl_xor_sync(0xffffffffu, rm1, 1));
        rm1 = fmaxf(rm1, __shfl_xor_sync(0xffffffffu, rm1, 2));
        const float nm0 = fmaxf(m0, rm0);
        const float nm1 = fmaxf(m1, rm1);
        const float al0 = __expf(m0 - nm0);
        const float al1 = __expf(m1 - nm1);
        m0 = nm0; m1 = nm1;

        float rs0 = 0.f, rs1 = 0.f;
#pragma unroll
        for (int nt = 0; nt < 8; nt++) {
            const float p0 = __expf(sacc[nt][0] * scale - m0);
            const float p1 = __expf(sacc[nt][1] * scale - m0);
            const float p2 = __expf(sacc[nt][2] * scale - m1);
            const float p3 = __expf(sacc[nt][3] * scale - m1);
            rs0 += p0 + p1; rs1 += p2 + p3;
            sacc[nt][0] = p0; sacc[nt][1] = p1; sacc[nt][2] = p2; sacc[nt][3] = p3;
        }
        rs0 += __shfl_xor_sync(0xffffffffu, rs0, 1);
        rs0 += __shfl_xor_sync(0xffffffffu, rs0, 2);
        rs1 += __shfl_xor_sync(0xffffffffu, rs1, 1);
        rs1 += __shfl_xor_sync(0xffffffffu, rs1, 2);
        l0 = l0 * al0 + rs0;
        l1 = l1 * al1 + rs1;
#pragma unroll
        for (int nt = 0; nt < 8; nt++) {
            o[nt][0] *= al0; o[nt][1] *= al0;
            o[nt][2] *= al1; o[nt][3] *= al1;
        }

        // P: C-frag -> A-frag purely in registers
        unsigned pa[4][4];
#pragma unroll
        for (int ks = 0; ks < 4; ks++) {
            pa[ks][0] = pk(sacc[2 * ks][0],     sacc[2 * ks][1]);
            pa[ks][1] = pk(sacc[2 * ks][2],     sacc[2 * ks][3]);
            pa[ks][2] = pk(sacc[2 * ks + 1][0], sacc[2 * ks + 1][1]);
            pa[ks][3] = pk(sacc[2 * ks + 1][2], sacc[2 * ks + 1][3]);
        }

        // O += P @ V (V via ldmatrix.trans)
#pragma unroll
        for (int nt = 0; nt < 8; nt++) {
            unsigned v0, v1, v2, v3, v4, v5, v6, v7;
            ldmx4t(v0, v1, v2, v3, vBase + (unsigned)((lane * KVST + nt * 4) * 4));        // k 0..31
            ldmx4t(v4, v5, v6, v7, vBase + (unsigned)(((lane + 32) * KVST + nt * 4) * 4)); // k 32..63
            mma16(o[nt][0], o[nt][1], o[nt][2], o[nt][3],
                  pa[0][0], pa[0][1], pa[0][2], pa[0][3], v0, v1);
            mma16(o[nt][0], o[nt][1], o[nt][2], o[nt][3],
                  pa[1][0], pa[1][1], pa[1][2], pa[1][3], v2, v3);
            mma16(o[nt][0], o[nt][1], o[nt][2], o[nt][3],
                  pa[2][0], pa[2][1], pa[2][2], pa[2][3], v4, v5);
            mma16(o[nt][0], o[nt][1], o[nt][2], o[nt][3],
                  pa[3][0], pa[3][1], pa[3][2], pa[3][3], v6, v7);
        }
    }

    const float inv0 = 1.0f / l0;
    const float inv1 = 1.0f / l1;
#pragma unroll
    for (int nt = 0; nt < 8; nt++) {
        const int c = nt * 8 + tig * 2;
        float2 lo = {o[nt][0] * inv0, o[nt][1] * inv0};
        float2 hi = {o[nt][2] * inv1, o[nt][3] * inv1};
        *(float2*)&Oh[(size_t)qr * DHH + c] = lo;
        *(float2*)&Oh[(size_t)(qr + 8) * DHH + c] = hi;
    }
}

// ---------------------------------------------------------------------------
// LayerNorm over rows of g_y -> d_out
// ---------------------------------------------------------------------------
__global__ __launch_bounds__(256) void ln_kernel(
    const float* __restrict__ gamma, const float* __restrict__ beta,
    float* __restrict__ out)
{
    const int row = blockIdx.x;
    const int tid = threadIdx.x;
    const float* y = g_y + (size_t)row * DD;

    float4 v = *reinterpret_cast<const float4*>(&y[tid * 4]);
    float sum = v.x + v.y + v.z + v.w;
    float sq  = v.x * v.x + v.y * v.y + v.z * v.z + v.w * v.w;

#pragma unroll
    for (int off = 16; off > 0; off >>= 1) {
        sum += __shfl_xor_sync(0xffffffffu, sum, off);
        sq  += __shfl_xor_sync(0xffffffffu, sq, off);
    }

    __shared__ float red[16];
    __shared__ float mean_s, rstd_s;
    const int warp = tid >> 5;
    if ((tid & 31) == 0) { red[warp] = sum; red[8 + warp] = sq; }
    __syncthreads();
    if (tid == 0) {
        float ts = 0.f, tq = 0.f;
#pragma unroll
        for (int w = 0; w < 8; w++) { ts += red[w]; tq += red[8 + w]; }
        float mu = ts * (1.0f / DD);
        float var = tq * (1.0f / DD) - mu * mu;
        mean_s = mu;
        rstd_s = rsqrtf(var + 1e-5f);
    }
    __syncthreads();
    const float mu = mean_s, rs = rstd_s;

    float4 g  = *reinterpret_cast<const float4*>(&gamma[tid * 4]);
    float4 bt = *reinterpret_cast<const float4*>(&beta[tid * 4]);
    float4 r;
    r.x = (v.x - mu) * rs * g.x + bt.x;
    r.y = (v.y - mu) * rs * g.y + bt.y;
    r.z = (v.z - mu) * rs * g.z + bt.z;
    r.w = (v.w - mu) * rs * g.w + bt.w;
    *reinterpret_cast<float4*>(&out[(size_t)row * DD + tid * 4]) = r;
}

// ---------------------------------------------------------------------------
extern "C" void kernel_launch(void* const* d_in, const int* in_sizes, int n_in,
                              void* d_out, int out_size)
{
    (void)in_sizes; (void)n_in; (void)out_size;
    const float* queries = (const float*)d_in[0];
    const float* keys    = (const float*)d_in[1];
    const float* values  = (const float*)d_in[2];
    const float* Wq = (const float*)d_in[3];
    const float* bq = (const float*)d_in[4];
    const float* Wk = (const float*)d_in[5];
    const float* bk = (const float*)d_in[6];
    const float* Wv = (const float*)d_in[7];
    const float* bv = (const float*)d_in[8];
    const float* Wo = (const float*)d_in[9];
    const float* bo = (const float*)d_in[10];
    const float* gamma = (const float*)d_in[11];
    const float* beta  = (const float*)d_in[12];

    dim3 gg(DD / 128, MM / 128);  // (8, 64)
    gemm_bf16_kernel<<<gg, 256>>>(queries, Wq, bq, nullptr, 0);
    gemm_bf16_kernel<<<gg, 256>>>(keys,    Wk, bk, nullptr, 1);
    gemm_bf16_kernel<<<gg, 256>>>(values,  Wv, bv, nullptr, 2);

    attn_bf16_kernel<<<dim3(SS / 128, BB * HH), 256>>>();

    gemm_bf16_kernel<<<gg, 256>>>(nullptr, Wo, bo, queries, 3);

    ln_kernel<<<MM, 256>>>(gamma, beta, (float*)d_out);
}

// round 6
// speedup vs baseline: 4.7285x; 1.0721x over previous
#include <cuda_runtime.h>
#include <cuda_bf16.h>

#define BB 4
#define SS 2048
#define DD 1024
#define HH 16
#define DHH 64
#define MM (BB * SS)   // 8192

// ---------------------------------------------------------------------------
// Scratch (device globals). Q/K/V kept in bf16 (rounding point identical to
// the previous in-attention conversion). attn output + pre-LN stay fp32.
// ---------------------------------------------------------------------------
__device__ __nv_bfloat16 g_q[MM * DD];
__device__ __nv_bfloat16 g_k[MM * DD];
__device__ __nv_bfloat16 g_v[MM * DD];
__device__ float g_attn[MM * DD];
__device__ float g_y[MM * DD];

// ---------------------------------------------------------------------------
// helpers
// ---------------------------------------------------------------------------
__device__ __forceinline__ unsigned pk(float lo, float hi) {
    unsigned r;
    asm("cvt.rn.bf16x2.f32 %0, %1, %2;" : "=r"(r) : "f"(hi), "f"(lo));
    return r;
}

__device__ __forceinline__ void mma16(float& c0, float& c1, float& c2, float& c3,
                                      unsigned a0, unsigned a1, unsigned a2, unsigned a3,
                                      unsigned b0, unsigned b1) {
    asm volatile(
        "mma.sync.aligned.m16n8k16.row.col.f32.bf16.bf16.f32 "
        "{%0,%1,%2,%3},{%4,%5,%6,%7},{%8,%9},{%0,%1,%2,%3};"
        : "+f"(c0), "+f"(c1), "+f"(c2), "+f"(c3)
        : "r"(a0), "r"(a1), "r"(a2), "r"(a3), "r"(b0), "r"(b1));
}

__device__ __forceinline__ void ldmx4(unsigned& r0, unsigned& r1, unsigned& r2, unsigned& r3,
                                      unsigned addr) {
    asm volatile("ldmatrix.sync.aligned.m8n8.x4.shared.b16 {%0,%1,%2,%3}, [%4];"
                 : "=r"(r0), "=r"(r1), "=r"(r2), "=r"(r3) : "r"(addr));
}

__device__ __forceinline__ void ldmx4t(unsigned& r0, unsigned& r1, unsigned& r2, unsigned& r3,
                                       unsigned addr) {
    asm volatile("ldmatrix.sync.aligned.m8n8.x4.trans.shared.b16 {%0,%1,%2,%3}, [%4];"
                 : "=r"(r0), "=r"(r1), "=r"(r2), "=r"(r3) : "r"(addr));
}

// ---------------------------------------------------------------------------
// BF16 GEMM: C[M,N] = A[M,K] @ W[K,N] + bias (+ residual)
// Block 128x128, BK=32, 256 thr, warp tile 64x32, m16n8k16 mma + ldmatrix.
// outsel 0..2 -> bf16 output (g_q/g_k/g_v); outsel 3 -> fp32 g_y (+residual).
// ---------------------------------------------------------------------------
#define ASTW 20   // words per As row (40 bf16)
#define BSTW 68   // words per Bs row (136 bf16)

__global__ __launch_bounds__(256, 2) void gemm_bf16_kernel(
    const float* __restrict__ Ain, const float* __restrict__ W,
    const float* __restrict__ bias, const float* __restrict__ Res, int outsel)
{
    const float* A = Ain ? Ain : g_attn;

    __shared__ unsigned As[128 * ASTW];  // 10240 B
    __shared__ unsigned Bs[32 * BSTW];   //  8704 B

    const int tid  = threadIdx.x;
    const int lane = tid & 31;
    const int warp = tid >> 5;
    const int wm   = warp >> 2;
    const int wn   = warp & 3;
    const int gid  = lane >> 2;
    const int tig  = lane & 3;
    const int brow = blockIdx.y * 128;
    const int bcol = blockIdx.x * 128;

    float acc[4][4][4];
#pragma unroll
    for (int mt = 0; mt < 4; mt++)
#pragma unroll
        for (int nt = 0; nt < 4; nt++)
#pragma unroll
            for (int r = 0; r < 4; r++) acc[mt][nt][r] = 0.f;

    const int ar  = tid >> 1;          // 0..127
    const int acg = (tid & 1) * 16;    // 0 or 16
    const int kr  = tid >> 3;          // 0..31
    const int ncg = (tid & 7) * 16;    // 0..112

    float4 av[4], bv[4];
#pragma unroll
    for (int u = 0; u < 4; u++) {
        av[u] = *(const float4*)&A[(size_t)(brow + ar) * DD + acg + 4 * u];
        bv[u] = *(const float4*)&W[(size_t)kr * DD + bcol + ncg + 4 * u];
    }

    const unsigned aBase = (unsigned)__cvta_generic_to_shared(As);
    const unsigned bBase = (unsigned)__cvta_generic_to_shared(Bs);
    const int arow_l = wm * 64 + (lane & 15);
    const int asel   = (lane >> 4) * 8;
    const int brow_l = lane & 15;
    const int bsel   = (lane >> 4) * 8;

    for (int it = 0; it < DD / 32; it++) {
#pragma unroll
        for (int u = 0; u < 4; u++) {
            As[ar * ASTW + ((acg + 4 * u) >> 1) + 0] = pk(av[u].x, av[u].y);
            As[ar * ASTW + ((acg + 4 * u) >> 1) + 1] = pk(av[u].z, av[u].w);
            Bs[kr * BSTW + ((ncg + 4 * u) >> 1) + 0] = pk(bv[u].x, bv[u].y);
            Bs[kr * BSTW + ((ncg + 4 * u) >> 1) + 1] = pk(bv[u].z, bv[u].w);
        }
        __syncthreads();

        if (it < DD / 32 - 1) {
            const int k0 = (it + 1) * 32;
#pragma unroll
            for (int u = 0; u < 4; u++) {
                av[u] = *(const float4*)&A[(size_t)(brow + ar) * DD + k0 + acg + 4 * u];
                bv[u] = *(const float4*)&W[(size_t)(k0 + kr) * DD + bcol + ncg + 4 * u];
            }
        }

#pragma unroll
        for (int ks = 0; ks < 2; ks++) {
            unsigned af[4][4];
#pragma unroll
            for (int mt = 0; mt < 4; mt++)
                ldmx4(af[mt][0], af[mt][1], af[mt][2], af[mt][3],
                      aBase + (unsigned)(((arow_l + mt * 16) * ASTW + ((ks * 16 + asel) >> 1)) * 4));

            unsigned bf[4][2];
#pragma unroll
            for (int ntp = 0; ntp < 2; ntp++) {
                unsigned r0, r1, r2, r3;
                ldmx4t(r0, r1, r2, r3,
                       bBase + (unsigned)(((ks * 16 + brow_l) * BSTW +
                                           ((wn * 32 + ntp * 16 + bsel) >> 1)) * 4));
                bf[2 * ntp + 0][0] = r0; bf[2 * ntp + 0][1] = r1;
                bf[2 * ntp + 1][0] = r2; bf[2 * ntp + 1][1] = r3;
            }
#pragma unroll
            for (int mt = 0; mt < 4; mt++)
#pragma unroll
                for (int nt = 0; nt < 4; nt++)
                    mma16(acc[mt][nt][0], acc[mt][nt][1], acc[mt][nt][2], acc[mt][nt][3],
                          af[mt][0], af[mt][1], af[mt][2], af[mt][3],
                          bf[nt][0], bf[nt][1]);
        }
        __syncthreads();
    }

    // epilogue
    if (outsel == 3) {
#pragma unroll
        for (int mt = 0; mt < 4; mt++) {
            const int r0 = brow + wm * 64 + mt * 16 + gid;
#pragma unroll
            for (int nt = 0; nt < 4; nt++) {
                const int c = bcol + wn * 32 + nt * 8 + tig * 2;
                const float bz0 = bias[c], bz1 = bias[c + 1];
                float x0 = acc[mt][nt][0] + bz0 + Res[(size_t)r0 * DD + c];
                float x1 = acc[mt][nt][1] + bz1 + Res[(size_t)r0 * DD + c + 1];
                float x2 = acc[mt][nt][2] + bz0 + Res[(size_t)(r0 + 8) * DD + c];
                float x3 = acc[mt][nt][3] + bz1 + Res[(size_t)(r0 + 8) * DD + c + 1];
                float2 lo = {x0, x1}, hi = {x2, x3};
                *(float2*)&g_y[(size_t)r0 * DD + c] = lo;
                *(float2*)&g_y[(size_t)(r0 + 8) * DD + c] = hi;
            }
        }
    } else {
        __nv_bfloat16* Cb = (outsel == 0) ? g_q : (outsel == 1) ? g_k : g_v;
#pragma unroll
        for (int mt = 0; mt < 4; mt++) {
            const int r0 = brow + wm * 64 + mt * 16 + gid;
#pragma unroll
            for (int nt = 0; nt < 4; nt++) {
                const int c = bcol + wn * 32 + nt * 8 + tig * 2;
                const float bz0 = bias[c], bz1 = bias[c + 1];
                *(unsigned*)&Cb[(size_t)r0 * DD + c] =
                    pk(acc[mt][nt][0] + bz0, acc[mt][nt][1] + bz1);
                *(unsigned*)&Cb[(size_t)(r0 + 8) * DD + c] =
                    pk(acc[mt][nt][2] + bz0, acc[mt][nt][3] + bz1);
            }
        }
    }
}

// ---------------------------------------------------------------------------
// BF16 flash attention v2: one (b,h) slab [2048,64] bf16.
// Block = 256 q rows, 8 warps; each warp owns 32 q rows (2 m16 tiles) so every
// K/V B-fragment feeds 2x the mma -> ldmatrix traffic per FLOP halves.
// KV tiles of 64; smem stride 72 bf16 (conflict-free ldmatrix).
// P packed to A-frags in registers inside the exp loop (no smem round trip).
// ---------------------------------------------------------------------------
#define KVST 36   // words per K/V row (72 bf16)

__global__ __launch_bounds__(256) void attn_bf16_kernel()
{
    __shared__ unsigned Ks[64 * KVST];  // 9216 B
    __shared__ unsigned Vs[64 * KVST];  // 9216 B

    const int tid  = threadIdx.x;
    const int lane = tid & 31;
    const int warp = tid >> 5;
    const int gid  = lane >> 2;
    const int tig  = lane & 3;

    const int bh = blockIdx.y;
    const int q0 = blockIdx.x * 256;
    const size_t base = (size_t)bh * SS * DHH;
    const __nv_bfloat16* Qh = g_q + base;
    const __nv_bfloat16* Kh = g_k + base;
    const __nv_bfloat16* Vh = g_v + base;
    float* Oh = g_attn + base;

    // Q fragments: 2 m-tiles x 4 k-steps (bf16 pairs loaded directly)
    unsigned qa[2][4][4];
    const int qr0 = q0 + warp * 32 + gid;
#pragma unroll
    for (int mt = 0; mt < 2; mt++) {
        const __nv_bfloat16* qp = Qh + (size_t)(qr0 + mt * 16) * DHH;
#pragma unroll
        for (int ks = 0; ks < 4; ks++) {
            const int c = ks * 16 + 2 * tig;
            qa[mt][ks][0] = *(const unsigned*)&qp[c];
            qa[mt][ks][1] = *(const unsigned*)&qp[8 * DHH + c];
            qa[mt][ks][2] = *(const unsigned*)&qp[c + 8];
            qa[mt][ks][3] = *(const unsigned*)&qp[8 * DHH + c + 8];
        }
    }

    float m[2][2], l[2][2];
#pragma unroll
    for (int mt = 0; mt < 2; mt++) { m[mt][0] = m[mt][1] = -1e30f; l[mt][0] = l[mt][1] = 0.f; }
    float o[2][8][4];
#pragma unroll
    for (int mt = 0; mt < 2; mt++)
#pragma unroll
        for (int nt = 0; nt < 8; nt++)
#pragma unroll
            for (int r = 0; r < 4; r++) o[mt][nt][r] = 0.f;

    const int lr  = tid >> 2;         // 0..63 (kv row)
    const int lcw = (tid & 3) * 8;    // word offset within row
    const float scale = 0.125f;

    const unsigned kBase = (unsigned)__cvta_generic_to_shared(Ks);
    const unsigned vBase = (unsigned)__cvta_generic_to_shared(Vs);
    const int krow_l = lane & 7;
    const int kgsel  = (lane >> 3) * 4;

    for (int kt = 0; kt < SS / 64; kt++) {
        __syncthreads();
        const __nv_bfloat16* Kp = Kh + (size_t)(kt * 64) * DHH;
        const __nv_bfloat16* Vp = Vh + (size_t)(kt * 64) * DHH;
#pragma unroll
        for (int u = 0; u < 2; u++) {
            uint4 kv = *(const uint4*)&Kp[lr * DHH + (lcw + u * 4) * 2];
            *(uint4*)&Ks[lr * KVST + lcw + u * 4] = kv;
            uint4 vv = *(const uint4*)&Vp[lr * DHH + (lcw + u * 4) * 2];
            *(uint4*)&Vs[lr * KVST + lcw + u * 4] = vv;
        }
        __syncthreads();

        // S = Q @ K^T (B-frags shared across both m-tiles)
        float sacc[2][8][4];
#pragma unroll
        for (int nt = 0; nt < 8; nt++) {
            unsigned b0, b1, b2, b3, b4, b5, b6, b7;
            const unsigned rowoff = (unsigned)(((nt * 8 + krow_l) * KVST) * 4);
            ldmx4(b0, b1, b2, b3, kBase + rowoff + (unsigned)(kgsel * 4));
            ldmx4(b4, b5, b6, b7, kBase + rowoff + (unsigned)((16 + kgsel) * 4));
#pragma unroll
            for (int mt = 0; mt < 2; mt++) {
                sacc[mt][nt][0] = sacc[mt][nt][1] = sacc[mt][nt][2] = sacc[mt][nt][3] = 0.f;
                mma16(sacc[mt][nt][0], sacc[mt][nt][1], sacc[mt][nt][2], sacc[mt][nt][3],
                      qa[mt][0][0], qa[mt][0][1], qa[mt][0][2], qa[mt][0][3], b0, b1);
                mma16(sacc[mt][nt][0], sacc[mt][nt][1], sacc[mt][nt][2], sacc[mt][nt][3],
                      qa[mt][1][0], qa[mt][1][1], qa[mt][1][2], qa[mt][1][3], b2, b3);
                mma16(sacc[mt][nt][0], sacc[mt][nt][1], sacc[mt][nt][2], sacc[mt][nt][3],
                      qa[mt][2][0], qa[mt][2][1], qa[mt][2][2], qa[mt][2][3], b4, b5);
                mma16(sacc[mt][nt][0], sacc[mt][nt][1], sacc[mt][nt][2], sacc[mt][nt][3],
                      qa[mt][3][0], qa[mt][3][1], qa[mt][3][2], qa[mt][3][3], b6, b7);
            }
        }

        // online softmax + pack P to A-frags, per m-tile
        unsigned pa[2][4][4];
#pragma unroll
        for (int mt = 0; mt < 2; mt++) {
            float rm0 = -1e30f, rm1 = -1e30f;
#pragma unroll
            for (int nt = 0; nt < 8; nt++) {
                rm0 = fmaxf(rm0, fmaxf(sacc[mt][nt][0], sacc[mt][nt][1]));
                rm1 = fmaxf(rm1, fmaxf(sacc[mt][nt][2], sacc[mt][nt][3]));
            }
            rm0 *= scale; rm1 *= scale;
            rm0 = fmaxf(rm0, __shfl_xor_sync(0xffffffffu, rm0, 1));
            rm0 = fmaxf(rm0, __shfl_xor_sync(0xffffffffu, rm0, 2));
            rm1 = fmaxf(rm1, __shfl_xor_sync(0xffffffffu, rm1, 1));
            rm1 = fmaxf(rm1, __shfl_xor_sync(0xffffffffu, rm1, 2));
            const float nm0 = fmaxf(m[mt][0], rm0);
            const float nm1 = fmaxf(m[mt][1], rm1);
            const float al0 = __expf(m[mt][0] - nm0);
            const float al1 = __expf(m[mt][1] - nm1);
            m[mt][0] = nm0; m[mt][1] = nm1;

            float rs0 = 0.f, rs1 = 0.f;
#pragma unroll
            for (int nt = 0; nt < 8; nt++) {
                const float p0 = __expf(sacc[mt][nt][0] * scale - nm0);
                const float p1 = __expf(sacc[mt][nt][1] * scale - nm0);
                const float p2 = __expf(sacc[mt][nt][2] * scale - nm1);
                const float p3 = __expf(sacc[mt][nt][3] * scale - nm1);
                rs0 += p0 + p1; rs1 += p2 + p3;
                if (nt & 1) {
                    pa[mt][nt >> 1][2] = pk(p0, p1);
                    pa[mt][nt >> 1][3] = pk(p2, p3);
                } else {
                    pa[mt][nt >> 1][0] = pk(p0, p1);
                    pa[mt][nt >> 1][1] = pk(p2, p3);
                }
            }
            rs0 += __shfl_xor_sync(0xffffffffu, rs0, 1);
            rs0 += __shfl_xor_sync(0xffffffffu, rs0, 2);
            rs1 += __shfl_xor_sync(0xffffffffu, rs1, 1);
            rs1 += __shfl_xor_sync(0xffffffffu, rs1, 2);
            l[mt][0] = l[mt][0] * al0 + rs0;
            l[mt][1] = l[mt][1] * al1 + rs1;
#pragma unroll
            for (int nt = 0; nt < 8; nt++) {
                o[mt][nt][0] *= al0; o[mt][nt][1] *= al0;
                o[mt][nt][2] *= al1; o[mt][nt][3] *= al1;
            }
        }

        // O += P @ V (V frags shared across both m-tiles)
#pragma unroll
        for (int nt = 0; nt < 8; nt++) {
            unsigned v0, v1, v2, v3, v4, v5, v6, v7;
            ldmx4t(v0, v1, v2, v3, vBase + (unsigned)((lane * KVST + nt * 4) * 4));
            ldmx4t(v4, v5, v6, v7, vBase + (unsigned)(((lane + 32) * KVST + nt * 4) * 4));
#pragma unroll
            for (int mt = 0; mt < 2; mt++) {
                mma16(o[mt][nt][0], o[mt][nt][1], o[mt][nt][2], o[mt][nt][3],
                      pa[mt][0][0], pa[mt][0][1], pa[mt][0][2], pa[mt][0][3], v0, v1);
                mma16(o[mt][nt][0], o[mt][nt][1], o[mt][nt][2], o[mt][nt][3],
                      pa[mt][1][0], pa[mt][1][1], pa[mt][1][2], pa[mt][1][3], v2, v3);
                mma16(o[mt][nt][0], o[mt][nt][1], o[mt][nt][2], o[mt][nt][3],
                      pa[mt][2][0], pa[mt][2][1], pa[mt][2][2], pa[mt][2][3], v4, v5);
                mma16(o[mt][nt][0], o[mt][nt][1], o[mt][nt][2], o[mt][nt][3],
                      pa[mt][3][0], pa[mt][3][1], pa[mt][3][2], pa[mt][3][3], v6, v7);
            }
        }
    }

    // normalize + write (fp32 out, feeds final GEMM)
#pragma unroll
    for (int mt = 0; mt < 2; mt++) {
        const int r = qr0 + mt * 16;
        const float inv0 = 1.0f / l[mt][0];
        const float inv1 = 1.0f / l[mt][1];
#pragma unroll
        for (int nt = 0; nt < 8; nt++) {
            const int c = nt * 8 + tig * 2;
            float2 lo = {o[mt][nt][0] * inv0, o[mt][nt][1] * inv0};
            float2 hi = {o[mt][nt][2] * inv1, o[mt][nt][3] * inv1};
            *(float2*)&Oh[(size_t)r * DHH + c] = lo;
            *(float2*)&Oh[(size_t)(r + 8) * DHH + c] = hi;
        }
    }
}

// ---------------------------------------------------------------------------
// LayerNorm over rows of g_y -> d_out
// ---------------------------------------------------------------------------
__global__ __launch_bounds__(256) void ln_kernel(
    const float* __restrict__ gamma, const float* __restrict__ beta,
    float* __restrict__ out)
{
    const int row = blockIdx.x;
    const int tid = threadIdx.x;
    const float* y = g_y + (size_t)row * DD;

    float4 v = *reinterpret_cast<const float4*>(&y[tid * 4]);
    float sum = v.x + v.y + v.z + v.w;
    float sq  = v.x * v.x + v.y * v.y + v.z * v.z + v.w * v.w;

#pragma unroll
    for (int off = 16; off > 0; off >>= 1) {
        sum += __shfl_xor_sync(0xffffffffu, sum, off);
        sq  += __shfl_xor_sync(0xffffffffu, sq, off);
    }

    __shared__ float red[16];
    __shared__ float mean_s, rstd_s;
    const int warp = tid >> 5;
    if ((tid & 31) == 0) { red[warp] = sum; red[8 + warp] = sq; }
    __syncthreads();
    if (tid == 0) {
        float ts = 0.f, tq = 0.f;
#pragma unroll
        for (int w = 0; w < 8; w++) { ts += red[w]; tq += red[8 + w]; }
        float mu = ts * (1.0f / DD);
        float var = tq * (1.0f / DD) - mu * mu;
        mean_s = mu;
        rstd_s = rsqrtf(var + 1e-5f);
    }
    __syncthreads();
    const float mu = mean_s, rs = rstd_s;

    float4 g  = *reinterpret_cast<const float4*>(&gamma[tid * 4]);
    float4 bt = *reinterpret_cast<const float4*>(&beta[tid * 4]);
    float4 r;
    r.x = (v.x - mu) * rs * g.x + bt.x;
    r.y = (v.y - mu) * rs * g.y + bt.y;
    r.z = (v.z - mu) * rs * g.z + bt.z;
    r.w = (v.w - mu) * rs * g.w + bt.w;
    *reinterpret_cast<float4*>(&out[(size_t)row * DD + tid * 4]) = r;
}

// ---------------------------------------------------------------------------
extern "C" void kernel_launch(void* const* d_in, const int* in_sizes, int n_in,
                              void* d_out, int out_size)
{
    (void)in_sizes; (void)n_in; (void)out_size;
    const float* queries = (const float*)d_in[0];
    const float* keys    = (const float*)d_in[1];
    const float* values  = (const float*)d_in[2];
    const float* Wq = (const float*)d_in[3];
    const float* bq = (const float*)d_in[4];
    const float* Wk = (const float*)d_in[5];
    const float* bk = (const float*)d_in[6];
    const float* Wv = (const float*)d_in[7];
    const float* bv = (const float*)d_in[8];
    const float* Wo = (const float*)d_in[9];
    const float* bo = (const float*)d_in[10];
    const float* gamma = (const float*)d_in[11];
    const float* beta  = (const float*)d_in[12];

    dim3 gg(DD / 128, MM / 128);  // (8, 64)
    gemm_bf16_kernel<<<gg, 256>>>(queries, Wq, bq, nullptr, 0);
    gemm_bf16_kernel<<<gg, 256>>>(keys,    Wk, bk, nullptr, 1);
    gemm_bf16_kernel<<<gg, 256>>>(values,  Wv, bv, nullptr, 2);

    attn_bf16_kernel<<<dim3(SS / 256, BB * HH), 256>>>();

    gemm_bf16_kernel<<<gg, 256>>>(nullptr, Wo, bo, queries, 3);

    ln_kernel<<<MM, 256>>>(gamma, beta, (float*)d_out);
}